// round 4
// baseline (speedup 1.0000x reference)
#include <cuda_runtime.h>
#include <cstdint>
#include <math.h>

#define SEQ   128
#define BATCH 32
#define EDIM  300
#define HID   200
#define NTAG  17
#define ROWS  (SEQ*BATCH)   // 4096
#define GN    1600          // 2 dirs * 4 gates * 200
#define NCD   50            // CTAs per direction in recurrent kernel
#define LTHREADS 512
#define FSTRIDE 64          // flag spread: 64 words = 256B (distinct L2 lines)

typedef unsigned long long ull;

#define FFMA2(acc, a, b) asm("fma.rn.f32x2 %0, %1, %2, %3;" : "=l"(acc) : "l"(a), "l"(b), "l"(acc))
#define SPLAT2(dst, f)   asm("mov.b64 %0, {%1, %1};" : "=l"(dst) : "r"(__float_as_uint(f)))

// ---------------- scratch (static device allocations) ----------------
__device__ float d_X0[ROWS*EDIM];    // gathered embeddings      (4096 x 300)
__device__ float d_G0[ROWS*GN];      // layer0 input projections (4096 x 1600)
__device__ float d_H0[ROWS*400];     // layer0 output            (4096 x 400)
__device__ float d_G1[ROWS*GN];      // layer1 input projections
__device__ float d_H1[ROWS*400];     // layer1 output
__device__ unsigned g_flags[4][NCD * FSTRIDE];  // barrier flags (layer*2 + dir)

__device__ __forceinline__ float fsig(float x) {
    return __fdividef(1.0f, 1.0f + __expf(-x));
}
__device__ __forceinline__ float ftanh(float x) {
    return 1.0f - __fdividef(2.0f, __expf(2.0f * x) + 1.0f);
}
// swizzled word base of h row b: all even b (and all odd b) land in 16 distinct 8B banks
__device__ __forceinline__ int hbase(int b) { return b * 208 + ((b >> 1) << 1); }
#define HWORDS 6688   // hbase(31)+200 = 6678, padded

// ---------------- flag reset ----------------
__global__ void reset_cnt_kernel() {
    int n = 4 * NCD * FSTRIDE;
    unsigned* p = &g_flags[0][0];
    for (int i = threadIdx.x + blockIdx.x * blockDim.x; i < n; i += blockDim.x * gridDim.x)
        p[i] = 0u;
}

// ---------------- embedding gather ----------------
__global__ void gather_kernel(const int* __restrict__ words,
                              const float* __restrict__ emb) {
    int idx = blockIdx.x * blockDim.x + threadIdx.x;
    if (idx >= ROWS * EDIM) return;
    int row = idx / EDIM;
    int e   = idx - row * EDIM;
    int t = row >> 5;
    int b = row & 31;
    int w = words[b * SEQ + t];
    d_X0[idx] = emb[(size_t)w * EDIM + e];
}

// ---------------- fp32 GEMM with FFMA2: C = A @ W^T + bias ----------------
__global__ __launch_bounds__(256)
void sgemm_bias_kernel(const float* __restrict__ A, const float* __restrict__ W,
                       const float* __restrict__ bias, float* __restrict__ C,
                       int M, int N, int K) {
    __shared__ __align__(16) float As[8][128];
    __shared__ __align__(16) float Bs[8][64];

    int tid = threadIdx.x;
    int tx = tid & 15;
    int ty = tid >> 4;
    int m0 = blockIdx.y * 128;
    int n0 = blockIdx.x * 64;

    ull acc2[4][4];
#pragma unroll
    for (int p = 0; p < 4; p++)
#pragma unroll
        for (int j = 0; j < 4; j++) acc2[p][j] = 0ull;

    int arow = tid >> 1;
    int ak   = (tid & 1) * 4;
    int brow = tid >> 2;
    int bk   = (tid & 3) * 2;

    const float* Arow = A + (size_t)(m0 + arow) * K;
    const float* Wrow = W + (size_t)(n0 + brow) * K;

    for (int k0 = 0; k0 < K; k0 += 8) {
#pragma unroll
        for (int j = 0; j < 4; j++) {
            int k = k0 + ak + j;
            As[ak + j][arow] = (k < K) ? Arow[k] : 0.f;
        }
#pragma unroll
        for (int j = 0; j < 2; j++) {
            int k = k0 + bk + j;
            Bs[bk + j][brow] = (k < K) ? Wrow[k] : 0.f;
        }
        __syncthreads();
#pragma unroll
        for (int kk = 0; kk < 8; kk++) {
            const ulonglong2* ap = (const ulonglong2*)&As[kk][ty * 8];
            ulonglong2 apA = ap[0], apB = ap[1];
            ull am2[4] = {apA.x, apA.y, apB.x, apB.y};
            float4 bv = *(const float4*)&Bs[kk][tx * 4];
            ull bs2[4];
            SPLAT2(bs2[0], bv.x); SPLAT2(bs2[1], bv.y);
            SPLAT2(bs2[2], bv.z); SPLAT2(bs2[3], bv.w);
#pragma unroll
            for (int p = 0; p < 4; p++)
#pragma unroll
                for (int j = 0; j < 4; j++)
                    FFMA2(acc2[p][j], am2[p], bs2[j]);
        }
        __syncthreads();
    }

    float4 bb = *(const float4*)&bias[n0 + tx * 4];
    float bn[4] = {bb.x, bb.y, bb.z, bb.w};
#pragma unroll
    for (int i = 0; i < 8; i++) {
        int m = m0 + ty * 8 + i;
        float4 v;
        float2 f0 = *((float2*)&acc2[i >> 1][0]);
        float2 f1 = *((float2*)&acc2[i >> 1][1]);
        float2 f2 = *((float2*)&acc2[i >> 1][2]);
        float2 f3 = *((float2*)&acc2[i >> 1][3]);
        v.x = ((i & 1) ? f0.y : f0.x) + bn[0];
        v.y = ((i & 1) ? f1.y : f1.x) + bn[1];
        v.z = ((i & 1) ? f2.y : f2.x) + bn[2];
        v.w = ((i & 1) ? f3.y : f3.x) + bn[3];
        *(float4*)&C[(size_t)m * N + n0 + tx * 4] = v;
    }
}

// ---------------- persistent bidirectional LSTM layer ----------------
// CTA (dir, cb): owns h cols j0..j0+3 -> 16 gate rows, all 32 batches.
// Matvec decode: bp=tid&15 (b pair), rp=(tid>>4)&7 (row pair), kq=tid>>7 (k quarter).
__global__ __launch_bounds__(LTHREADS, 1)
void lstm_layer_kernel(const float* __restrict__ G, const float* __restrict__ Whh,
                       float* __restrict__ H, unsigned* flags) {
    __shared__ __align__(16) float sh_U[16 * 200];     // 12800 B
    __shared__ __align__(16) float sh_h[HWORDS];       // 26752 B (swizzled rows)
    __shared__ float sh_part[4 * 528];                 // 8448 B (stride 33)

    int tid = threadIdx.x;
    int dir = blockIdx.x / NCD;
    int cb  = blockIdx.x % NCD;
    int j0  = cb * 4;
    unsigned* myflags = flags + dir * (NCD * FSTRIDE);
    unsigned* myflag  = myflags + cb * FSTRIDE;

    // preload U rows
    const float* Ud = Whh + (size_t)dir * 800 * 200;
    for (int idx = tid; idx < 16 * 200; idx += LTHREADS) {
        int r = idx / 200, k = idx - r * 200;
        int g = r >> 2, q = r & 3;
        sh_U[idx] = Ud[(size_t)(g * 200 + j0 + q) * 200 + k];
    }
    for (int idx = tid; idx < HWORDS; idx += LTHREADS) sh_h[idx] = 0.f;
    __syncthreads();

    int bp = tid & 15;
    int rp = (tid >> 4) & 7;
    int kq = tid >> 7;
    int b0 = 2 * bp, b1 = b0 + 1;
    int r0 = 2 * rp, r1 = r0 + 1;

    const ull* pu0 = (const ull*)(sh_U + r0 * 200) + kq * 25;
    const ull* pu1 = (const ull*)(sh_U + r1 * 200) + kq * 25;
    const ull* ph0 = (const ull*)(sh_h + hbase(b0)) + kq * 25;
    const ull* ph1 = (const ull*)(sh_h + hbase(b1)) + kq * 25;

    // epilogue thread identity (tid < 128): col q, batch b
    int eq = tid >> 5;
    int eb = tid & 31;
    float creg = 0.f;
    const float* Gbase = G + dir * 800 + (j0 + eq) + (size_t)eb * GN;

    // polling identity (warp 0): lane handles flags idx lane and lane+32
    int lane = tid & 31;
    const unsigned* pf0 = myflags + lane * FSTRIDE;
    const unsigned* pf1 = myflags + (lane + 32) * FSTRIDE;
    bool f1valid = (lane + 32) < NCD;

    // G prefetch for step 0
    float gi = 0.f, gf = 0.f, gg = 0.f, go = 0.f;
    {
        int t0 = dir ? (SEQ - 1) : 0;
        if (tid < 128) {
            const float* Gp = Gbase + (size_t)t0 * (32 * GN);
            gi = __ldg(Gp); gf = __ldg(Gp + 200);
            gg = __ldg(Gp + 400); go = __ldg(Gp + 600);
        }
    }

    for (int step = 0; step < SEQ; step++) {
        int t = dir ? (SEQ - 1 - step) : step;

        // load h_{t-1} into swizzled smem
        if (step > 0) {
            int tp = dir ? (t + 1) : (t - 1);
            const float* Hp = H + dir * 200;
            for (int idx = tid; idx < 32 * 50; idx += LTHREADS) {
                int bb = idx / 50;
                int j4 = (idx - bb * 50) * 4;
                float4 v = __ldcg((const float4*)&Hp[(size_t)(tp * 32 + bb) * 400 + j4]);
                ull* dst = (ull*)(sh_h + hbase(bb) + j4);
                dst[0] = ((ull*)&v)[0];
                dst[1] = ((ull*)&v)[1];
            }
        }
        __syncthreads();

        // matvec: 2 rows x 2 batches, K-slice of 50 (25 u64 pairs)
        ull a00 = 0ull, a01 = 0ull, a10 = 0ull, a11 = 0ull;
#pragma unroll
        for (int kk = 0; kk < 25; kk++) {
            ull h0v = ph0[kk];
            ull h1v = ph1[kk];
            ull u0v = pu0[kk];
            ull u1v = pu1[kk];
            FFMA2(a00, u0v, h0v);
            FFMA2(a01, u0v, h1v);
            FFMA2(a10, u1v, h0v);
            FFMA2(a11, u1v, h1v);
        }
        {
            float2 f;
            float* P = sh_part + kq * 528;
            f = *(float2*)&a00; P[r0 * 33 + b0] = f.x + f.y;
            f = *(float2*)&a01; P[r0 * 33 + b1] = f.x + f.y;
            f = *(float2*)&a10; P[r1 * 33 + b0] = f.x + f.y;
            f = *(float2*)&a11; P[r1 * 33 + b1] = f.x + f.y;
        }
        __syncthreads();

        // epilogue: combine partials, gates -> c,h; publish h slice
        if (tid < 128) {
            float y[4];
#pragma unroll
            for (int g = 0; g < 4; g++) {
                int r = 4 * g + eq;
                y[g] = sh_part[0 * 528 + r * 33 + eb] + sh_part[1 * 528 + r * 33 + eb]
                     + sh_part[2 * 528 + r * 33 + eb] + sh_part[3 * 528 + r * 33 + eb];
            }
            float yi = y[0] + gi;
            float yf = y[1] + gf;
            float yg = y[2] + gg;
            float yo = y[3] + go;
            float c = fsig(yf) * creg + fsig(yi) * ftanh(yg);
            float hn = fsig(yo) * ftanh(c);
            creg = c;
            H[(size_t)(t * 32 + eb) * 400 + dir * 200 + (j0 + eq)] = hn;
        }
        __syncthreads();

        if (step < SEQ - 1) {
            // prefetch G for NEXT step so LDG latency hides under the barrier
            int tn = dir ? (t - 1) : (t + 1);
            if (tid < 128) {
                const float* Gp = Gbase + (size_t)tn * (32 * GN);
                gi = __ldg(Gp); gf = __ldg(Gp + 200);
                gg = __ldg(Gp + 400); go = __ldg(Gp + 600);
            }

            unsigned target = (unsigned)(step + 1);
            // arrive: one release store to our own spread slot
            if (tid == 0) {
                asm volatile("st.release.gpu.global.u32 [%0], %1;"
                             :: "l"(myflag), "r"(target) : "memory");
            }
            // wait: warp 0 polls all flags in parallel
            if (tid < 32) {
                bool done;
                do {
                    unsigned v0, v1 = target;
                    asm volatile("ld.acquire.gpu.global.u32 %0, [%1];"
                                 : "=r"(v0) : "l"(pf0) : "memory");
                    if (f1valid)
                        asm volatile("ld.acquire.gpu.global.u32 %0, [%1];"
                                     : "=r"(v1) : "l"(pf1) : "memory");
                    done = (v0 >= target) && (v1 >= target);
                } while (__ballot_sync(0xffffffffu, done) != 0xffffffffu);
            }
            __syncthreads();
        }
    }
}

// ---------------- output head ----------------
__global__ void out_kernel(const float* __restrict__ ow, const float* __restrict__ ob,
                           float* __restrict__ out) {
    int row  = blockIdx.x;           // = s*32 + b
    int warp = threadIdx.x >> 5;     // 0..16 = tag
    int lane = threadIdx.x & 31;
    const float* h    = d_H1 + (size_t)row * 400;
    const float* wrow = ow + warp * 400;
    float sum = 0.f;
#pragma unroll
    for (int k = lane; k < 400; k += 32) sum = fmaf(h[k], wrow[k], sum);
#pragma unroll
    for (int o = 16; o; o >>= 1) sum += __shfl_down_sync(0xffffffffu, sum, o);
    if (lane == 0) {
        int s = row >> 5, b = row & 31;
        out[((size_t)b * SEQ + s) * NTAG + warp] = fsig(sum + ob[warp]);
    }
}

// ---------------- launch ----------------
extern "C" void kernel_launch(void* const* d_in, const int* in_sizes, int n_in,
                              void* d_out, int out_size) {
    const int*   words = (const int*)  d_in[0];
    const float* emb   = (const float*)d_in[3];
    const float* Wih0  = (const float*)d_in[7];
    const float* Whh0  = (const float*)d_in[8];
    const float* b0    = (const float*)d_in[9];
    const float* Wih1  = (const float*)d_in[10];
    const float* Whh1  = (const float*)d_in[11];
    const float* b1    = (const float*)d_in[12];
    const float* ow    = (const float*)d_in[13];
    const float* ob    = (const float*)d_in[14];
    float* out = (float*)d_out;

    float *pX0, *pG0, *pH0, *pG1, *pH1;
    unsigned* pflags;
    cudaGetSymbolAddress((void**)&pX0, d_X0);
    cudaGetSymbolAddress((void**)&pG0, d_G0);
    cudaGetSymbolAddress((void**)&pH0, d_H0);
    cudaGetSymbolAddress((void**)&pG1, d_G1);
    cudaGetSymbolAddress((void**)&pH1, d_H1);
    cudaGetSymbolAddress((void**)&pflags, g_flags);

    reset_cnt_kernel<<<13, 512>>>();

    gather_kernel<<<(ROWS * EDIM + 255) / 256, 256>>>(words, emb);

    dim3 gdim0(GN / 64, ROWS / 128);
    sgemm_bias_kernel<<<gdim0, 256>>>(pX0, Wih0, b0, pG0, ROWS, GN, EDIM);

    lstm_layer_kernel<<<2 * NCD, LTHREADS>>>(pG0, Whh0, pH0, pflags + 0 * NCD * FSTRIDE);

    sgemm_bias_kernel<<<gdim0, 256>>>(pH0, Wih1, b1, pG1, ROWS, GN, 400);

    lstm_layer_kernel<<<2 * NCD, LTHREADS>>>(pG1, Whh1, pH1, pflags + 2 * NCD * FSTRIDE);

    out_kernel<<<ROWS, NTAG * 32>>>(ow, ob, out);
}